// round 1
// baseline (speedup 1.0000x reference)
#include <cuda_runtime.h>
#include <math.h>

#define NMAX 100000
#define C    64
#define HID  16
#define KNN  16
#define FULL 0xFFFFFFFFu

// Scratch (device globals: no allocation allowed in kernel_launch)
__device__ float g_outse[(size_t)NMAX * C];   // stage-1 output (gated features)
__device__ float g_rowstat[(size_t)NMAX * 2]; // per-point (rowsum, rowmax) of outse
__device__ float g_z[(size_t)NMAX * 2];       // stage-2 (mean, max) pooled stats

// ---------------------------------------------------------------------------
// Kernel 1: channel attention. warp-per-point.
//   gather 16 neighbor rows (coalesced 256B each), mean/max pool,
//   shared MLP on both pooled vectors, sigmoid gate, outse = x * gate.
//   Also emits rowsum/rowmax of outse for stage 2.
// ---------------------------------------------------------------------------
__global__ __launch_bounds__(256) void k1_gate(
    const float* __restrict__ xF,
    const float* __restrict__ W1,   // (C, HID)
    const float* __restrict__ b1,   // (HID,)
    const float* __restrict__ W2,   // (HID, C)
    const float* __restrict__ b2,   // (C,)
    const int*   __restrict__ idx,  // (N, KNN)
    int N)
{
    __shared__ float sW1t[HID * C];  // transposed: [j][c] for conflict-free float2 reads
    __shared__ float sW2 [HID * C];  // already [j][c]
    __shared__ float sb1[HID];
    __shared__ float sb2[C];

    const int tid = threadIdx.x;
    for (int i = tid; i < HID * C; i += blockDim.x) {
        int c = i / HID, j = i % HID;       // W1 element (c, j)
        sW1t[j * C + c] = W1[i];
        sW2[i] = W2[i];
    }
    if (tid < HID) sb1[tid] = b1[tid];
    if (tid < C)   sb2[tid] = b2[tid];
    __syncthreads();

    const int n    = (blockIdx.x * blockDim.x + tid) >> 5;
    const int lane = tid & 31;
    if (n >= N) return;

    // ---- load neighbor indices (lane-uniform, L1 broadcast) ----
    int nb[KNN];
    const int* ib = idx + (size_t)n * KNN;
    #pragma unroll
    for (int k = 0; k < KNN; k++) nb[k] = __ldg(ib + k);

    // ---- gather + pool: lane owns channels 2l, 2l+1 ----
    float m0 = 0.f, m1 = 0.f, x0 = -INFINITY, x1 = -INFINITY;
    #pragma unroll
    for (int k = 0; k < KNN; k++) {
        float2 v = __ldg((const float2*)(xF + (size_t)nb[k] * C + 2 * lane));
        m0 += v.x; m1 += v.y;
        x0 = fmaxf(x0, v.x); x1 = fmaxf(x1, v.y);
    }
    m0 *= (1.f / KNN); m1 *= (1.f / KNN);

    // ---- layer-1 partials: p[j]=mean-path unit j, p[j+16]=max-path unit j ----
    float p[32];
    #pragma unroll
    for (int j = 0; j < HID; j++) {
        float2 w = *(const float2*)(sW1t + j * C + 2 * lane);
        p[j]      = m0 * w.x + m1 * w.y;
        p[j + 16] = x0 * w.x + x1 * w.y;
    }

    // ---- vector-halving butterfly: 31 shfls reduce all 32 partials.
    //      After 5 rounds, lane l holds the full sum of element l in p[0]. ----
    #pragma unroll
    for (int step = 0; step < 5; step++) {
        const int off = 16 >> step;
        const int nv  = 16 >> step;
        const bool up = (lane & off) != 0;
        #pragma unroll
        for (int i = 0; i < nv; i++) {
            float send = up ? p[i] : p[i + nv];
            float recv = __shfl_xor_sync(FULL, send, off);
            float keep = up ? p[i + nv] : p[i];
            p[i] = keep + recv;
        }
    }

    // lane<16: mean-path hidden unit 'lane'; lane>=16: max-path unit 'lane-16'
    float h  = fmaxf(p[0] + sb1[lane & 15], 0.f);            // relu(v@W1+b1)
    float hs = h + __shfl_xor_sync(FULL, h, 16);             // h_mean[j]+h_max[j] on lane j

    // ---- layer 2: gate_logit[c] = 2*b2[c] + sum_j hs[j]*W2[j][c] ----
    float a0 = 2.f * sb2[2 * lane], a1 = 2.f * sb2[2 * lane + 1];
    #pragma unroll
    for (int j = 0; j < HID; j++) {
        float  hj = __shfl_sync(FULL, hs, j);
        float2 w  = *(const float2*)(sW2 + j * C + 2 * lane);
        a0 += hj * w.x; a1 += hj * w.y;
    }

    float2 xv = __ldg((const float2*)(xF + (size_t)n * C + 2 * lane));
    float g0 = 1.f / (1.f + expf(-a0));
    float g1 = 1.f / (1.f + expf(-a1));
    float o0 = xv.x * g0, o1 = xv.y * g1;
    *(float2*)(g_outse + (size_t)n * C + 2 * lane) = make_float2(o0, o1);

    // ---- rowsum/rowmax of outse for the factored stage-2 pooling ----
    float s  = o0 + o1;
    float mx = fmaxf(o0, o1);
    #pragma unroll
    for (int off = 16; off >= 1; off >>= 1) {
        s  += __shfl_xor_sync(FULL, s, off);
        mx  = fmaxf(mx, __shfl_xor_sync(FULL, mx, off));
    }
    if (lane == 0) {
        g_rowstat[2 * (size_t)n]     = s;
        g_rowstat[2 * (size_t)n + 1] = mx;
    }
}

// ---------------------------------------------------------------------------
// Kernel 2: z = (mean over k*c, max over k*c) of outse[idx], factored through
//           per-point rowstats. thread-per-point, 16 x 8B gathers.
// ---------------------------------------------------------------------------
__global__ __launch_bounds__(256) void k2_z(const int* __restrict__ idx, int N)
{
    int n = blockIdx.x * blockDim.x + threadIdx.x;
    if (n >= N) return;
    const int* ib = idx + (size_t)n * KNN;
    float s = 0.f, mx = -INFINITY;
    #pragma unroll
    for (int k = 0; k < KNN; k++) {
        int nb = __ldg(ib + k);
        float2 rs = __ldg((const float2*)(g_rowstat + 2 * (size_t)nb));
        s += rs.x;
        mx = fmaxf(mx, rs.y);
    }
    g_z[2 * (size_t)n]     = s * (1.f / (KNN * C));
    g_z[2 * (size_t)n + 1] = mx;
}

// ---------------------------------------------------------------------------
// Kernel 3: sparse conv3d(2->1) over 27 voxel neighbors + final gating.
//           warp-per-point: lanes 0..26 each handle one conv tap.
// ---------------------------------------------------------------------------
__global__ __launch_bounds__(256) void k3_out(
    const float* __restrict__ conv_w,   // (27, 2, 1)
    const int*   __restrict__ conv_idx, // (N, 27)
    float*       __restrict__ out,
    int N)
{
    const int n    = (blockIdx.x * blockDim.x + threadIdx.x) >> 5;
    const int lane = threadIdx.x & 31;
    if (n >= N) return;

    float f = 0.f;
    if (lane < 27) {
        int m = __ldg(conv_idx + (size_t)n * 27 + lane);
        if (m >= 0) {
            float2 zz = __ldg((const float2*)(g_z + 2 * (size_t)m));
            float2 cw = __ldg((const float2*)(conv_w + 2 * lane));
            f = zz.x * cw.x + zz.y * cw.y;
        }
    }
    #pragma unroll
    for (int off = 16; off >= 1; off >>= 1)
        f += __shfl_xor_sync(FULL, f, off);

    float sg = 1.f / (1.f + expf(-f));
    float2 o = *(const float2*)(g_outse + (size_t)n * C + 2 * lane);
    *(float2*)(out + (size_t)n * C + 2 * lane) = make_float2(o.x * sg, o.y * sg);
}

// ---------------------------------------------------------------------------
// Launch: inputs in metadata order:
//   0 x_F (N*C f32), 1 W1 (C*HID), 2 b1 (HID), 3 W2 (HID*C), 4 b2 (C),
//   5 conv_w (27*2), 6 idx (N*KNN i32), 7 conv_idx (N*27 i32)
// ---------------------------------------------------------------------------
extern "C" void kernel_launch(void* const* d_in, const int* in_sizes, int n_in,
                              void* d_out, int out_size)
{
    const float* xF  = (const float*)d_in[0];
    const float* W1  = (const float*)d_in[1];
    const float* b1  = (const float*)d_in[2];
    const float* W2  = (const float*)d_in[3];
    const float* b2  = (const float*)d_in[4];
    const float* cw  = (const float*)d_in[5];
    const int*   idx = (const int*)d_in[6];
    const int*   cid = (const int*)d_in[7];
    float*       out = (float*)d_out;

    const int N = in_sizes[0] / C;                 // 100000
    const int warpBlocks = (N + 7) / 8;            // 8 warps (points) per 256-thr block

    k1_gate<<<warpBlocks, 256>>>(xF, W1, b1, W2, b2, idx, N);
    k2_z  <<<(N + 255) / 256, 256>>>(idx, N);
    k3_out<<<warpBlocks, 256>>>(cw, cid, out, N);
}